// round 3
// baseline (speedup 1.0000x reference)
#include <cuda_runtime.h>
#include <math.h>

// GRU problem constants
#define T_SEQ 1024
#define BATCH 32
#define HID   512
#define H3    1536   // 3*HID
#define LAYERS 3

// ---------------------------------------------------------------------------
// Scratch (device globals — no runtime allocation allowed)
// ---------------------------------------------------------------------------
// Xi for current layer, both directions: [dir][t][gate_row 0..1535][batch]
__device__ float g_xi[2][T_SEQ][H3][BATCH];
// Layer outputs (concat fwd|bwd along feature): [buf][t][batch][2H]
__device__ float g_y[2][T_SEQ][BATCH][2 * HID];
// Hidden state double buffer, stored transposed [k][batch]
__device__ float g_h[2][2][HID][BATCH];              // [buf][dir][j][b]
// Per-direction step barrier counters
__device__ unsigned g_bar[2];

// ---------------------------------------------------------------------------
// f32x2 packed-FMA helpers (sm_100+; only reachable via PTX)
// ---------------------------------------------------------------------------
__device__ __forceinline__ unsigned long long dup2(float x) {
    unsigned long long r;
    asm("mov.b64 %0, {%1, %1};" : "=l"(r) : "f"(x));
    return r;
}
__device__ __forceinline__ void ffma2(unsigned long long& d,
                                      unsigned long long a,
                                      unsigned long long b) {
    asm("fma.rn.f32x2 %0, %1, %2, %0;" : "+l"(d) : "l"(a), "l"(b));
}
__device__ __forceinline__ float2 unpk(unsigned long long v) {
    float2 f;
    asm("mov.b64 {%0, %1}, %2;" : "=f"(f.x), "=f"(f.y) : "l"(v));
    return f;
}

// ---------------------------------------------------------------------------
// Zero hidden state (both buffers, both dirs) + reset barrier counters
// ---------------------------------------------------------------------------
__global__ void zero_h_kernel() {
    int idx = blockIdx.x * blockDim.x + threadIdx.x;
    float* p = &g_h[0][0][0][0];                      // 65536 floats total
    int i = idx * 4;
    if (i < 2 * 2 * HID * BATCH) {
        *(float4*)&p[i] = make_float4(0.f, 0.f, 0.f, 0.f);
    }
    if (idx == 0) { g_bar[0] = 0u; g_bar[1] = 0u; }
}

// ---------------------------------------------------------------------------
// Input projection: Xi[d][t][g][b] = sum_k A[(t,b),k] * W[d][g][k] + b_ih[d][g]
// Tiled 64x64x16 SGEMM, 4x4 register tile, f32x2 packed FMA (j-pairs).
// src: 0 -> external x pointer, 1 -> g_y[0], 2 -> g_y[1]
// ---------------------------------------------------------------------------
__global__ __launch_bounds__(256) void proj_kernel(
    const float* __restrict__ x0,
    const float* __restrict__ W,      // (2, 1536, K)
    const float* __restrict__ bih,    // (2, 1536)
    int K, int src)
{
    const float* A = (src == 0) ? x0 : &g_y[src - 1][0][0][0];

    int d  = blockIdx.z;
    int n0 = blockIdx.x * 64;   // gate-row tile
    int m0 = blockIdx.y * 64;   // (t,b) row tile
    const float* Wd = W + (size_t)d * H3 * K;
    const float* bd = bih + d * H3;

    __shared__ float As[16][64];
    __shared__ float Bs[16][64];

    int tid  = threadIdx.x;
    int lrow = tid >> 2;            // 0..63
    int lq   = (tid & 3) << 2;      // 0,4,8,12
    int tx   = tid & 15;
    int ty   = tid >> 4;

    unsigned long long acc[4][2];   // acc[i][jp] = (c[i][2jp], c[i][2jp+1])
#pragma unroll
    for (int i = 0; i < 4; i++) { acc[i][0] = 0ull; acc[i][1] = 0ull; }

    for (int k0 = 0; k0 < K; k0 += 16) {
        float4 a4 = *(const float4*)&A [(size_t)(m0 + lrow) * K + k0 + lq];
        float4 b4 = *(const float4*)&Wd[(size_t)(n0 + lrow) * K + k0 + lq];
        As[lq + 0][lrow] = a4.x; As[lq + 1][lrow] = a4.y;
        As[lq + 2][lrow] = a4.z; As[lq + 3][lrow] = a4.w;
        Bs[lq + 0][lrow] = b4.x; Bs[lq + 1][lrow] = b4.y;
        Bs[lq + 2][lrow] = b4.z; Bs[lq + 3][lrow] = b4.w;
        __syncthreads();
#pragma unroll
        for (int kk = 0; kk < 16; kk++) {
            float4 av = *(const float4*)&As[kk][ty << 2];
            ulonglong2 bp = *(const ulonglong2*)&Bs[kk][tx << 2];
            unsigned long long a0 = dup2(av.x);
            unsigned long long a1 = dup2(av.y);
            unsigned long long a2 = dup2(av.z);
            unsigned long long a3 = dup2(av.w);
            ffma2(acc[0][0], a0, bp.x); ffma2(acc[0][1], a0, bp.y);
            ffma2(acc[1][0], a1, bp.x); ffma2(acc[1][1], a1, bp.y);
            ffma2(acc[2][0], a2, bp.x); ffma2(acc[2][1], a2, bp.y);
            ffma2(acc[3][0], a3, bp.x); ffma2(acc[3][1], a3, bp.y);
        }
        __syncthreads();
    }

#pragma unroll
    for (int i = 0; i < 4; i++) {
        int m = m0 + (ty << 2) + i;
        int t = m >> 5;
        int b = m & 31;
        float2 c01 = unpk(acc[i][0]);
        float2 c23 = unpk(acc[i][1]);
        int g = n0 + (tx << 2);
        g_xi[d][t][g + 0][b] = c01.x + bd[g + 0];
        g_xi[d][t][g + 1][b] = c01.y + bd[g + 1];
        g_xi[d][t][g + 2][b] = c23.x + bd[g + 2];
        g_xi[d][t][g + 3][b] = c23.y + bd[g + 3];
    }
}

// ---------------------------------------------------------------------------
// Persistent recurrent kernel: one launch per layer, loops all 1024 steps.
// grid = (64 j-blocks, 2 dirs) = 128 CTAs, 256 threads, 112KB dyn smem
// -> exactly 1 CTA per SM, 128 <= 148 SMs => all co-resident (spin-safe).
// W_hh slice staged to smem ONCE; h exchanged via global (__ldcg) + barrier.
// ---------------------------------------------------------------------------
#define STEP_SMEM ((3 * 8 * 512 + 512 * 32) * 4)

__global__ __launch_bounds__(256) void gru_layer_kernel(
    const float* __restrict__ whh,   // (2, 1536, 512)
    const float* __restrict__ bhh,   // (2, 1536)
    float* __restrict__ dout,        // (6, 32, 512)
    int layer, int ydst)
{
    extern __shared__ float sm[];
    float* sW = sm;                  // [3][8][512]
    float* sH = sm + 3 * 8 * 512;    // [512][32]

    int d   = blockIdx.y;
    int j0  = blockIdx.x * 8;
    int tid = threadIdx.x;
    int b   = tid & 31;
    int jl  = tid >> 5;
    int j   = j0 + jl;

    // ---- Stage W_hh rows {j0..j0+7} for gates r,z,n (once per layer) ----
    const float* wd = whh + (size_t)d * H3 * HID;
#pragma unroll
    for (int it = 0; it < 12; it++) {
        int idx  = it * 256 + tid;       // float4 units, 0..3071
        int row  = idx >> 7;             // 0..23
        int q    = (idx & 127) << 2;
        int gate = row >> 3;
        int r    = row & 7;
        *(float4*)&sW[(gate * 8 + r) * 512 + q] =
            *(const float4*)&wd[(size_t)(gate * 512 + j0 + r) * 512 + q];
    }
    const float* bd = bhh + d * H3;
    float br = bd[j], bz = bd[HID + j], bn = bd[2 * HID + j];
    const float* wr_ = &sW[(0 * 8 + jl) * 512];
    const float* wz_ = &sW[(1 * 8 + jl) * 512];
    const float* wn_ = &sW[(2 * 8 + jl) * 512];
    __syncthreads();

    unsigned target = 0;

    for (int s = 0; s < T_SEQ; s++) {
        int t = d ? (T_SEQ - 1 - s) : s;

        // Prefetch Xi for this (t, j, b) early (hides DRAM latency)
        float xr = g_xi[d][t][j][b];
        float xz = g_xi[d][t][HID + j][b];
        float xn = g_xi[d][t][2 * HID + j][b];

        // Stage h (L1-bypassing reads; written by other CTAs last step)
        const float* hin = &g_h[s & 1][d][0][0];
#pragma unroll
        for (int it = 0; it < 16; it++) {
            int idx = (it * 256 + tid) << 2;
            float4 v = __ldcg((const float4*)&hin[idx]);
            *(float4*)&sH[idx] = v;
        }
        __syncthreads();

        float ar = 0.f, az = 0.f, an = 0.f;
#pragma unroll 8
        for (int k = 0; k < HID; k += 4) {
            float4 wr = *(const float4*)&wr_[k];
            float4 wz = *(const float4*)&wz_[k];
            float4 wn = *(const float4*)&wn_[k];
            float h0 = sH[(k + 0) * 32 + b];
            float h1 = sH[(k + 1) * 32 + b];
            float h2 = sH[(k + 2) * 32 + b];
            float h3 = sH[(k + 3) * 32 + b];
            ar += wr.x * h0 + wr.y * h1 + wr.z * h2 + wr.w * h3;
            az += wz.x * h0 + wz.y * h1 + wz.z * h2 + wz.w * h3;
            an += wn.x * h0 + wn.y * h1 + wn.z * h2 + wn.w * h3;
        }

        float r = 1.f / (1.f + expf(-(xr + ar + br)));
        float z = 1.f / (1.f + expf(-(xz + az + bz)));
        float n = tanhf(xn + r * (an + bn));
        float hold = sH[j * 32 + b];
        float hnew = (1.f - z) * n + z * hold;

        g_h[(s & 1) ^ 1][d][j][b] = hnew;
        g_y[ydst][t][b][d * HID + j] = hnew;
        if (s == T_SEQ - 1) {
            dout[((layer * 2 + d) * BATCH + b) * HID + j] = hnew;
        }

        // ---- Grid barrier (per direction) ----
        __threadfence();       // make this thread's h store GPU-visible
        __syncthreads();       // all CTA threads done (canonical fence+sync)
        target += 64;
        if (tid == 0) {
            atomicAdd(&g_bar[d], 1u);
            while (((volatile unsigned*)g_bar)[d] < target) { }
        }
        __syncthreads();
        __threadfence();       // acquire: order subsequent h reads after spin
    }
}

// ---------------------------------------------------------------------------
// kernel_launch: 3 layers x (zero_h + proj + persistent layer) = 9 graph nodes
// ---------------------------------------------------------------------------
extern "C" void kernel_launch(void* const* d_in, const int* in_sizes, int n_in,
                              void* d_out, int out_size)
{
    const float* x        = (const float*)d_in[0];
    const float* w_ih_l0  = (const float*)d_in[1];
    const float* w_hh_l0  = (const float*)d_in[2];
    const float* b_ih_l0  = (const float*)d_in[3];
    const float* b_hh_l0  = (const float*)d_in[4];
    const float* w_ih_lr  = (const float*)d_in[5];
    const float* w_hh_lr  = (const float*)d_in[6];
    const float* b_ih_lr  = (const float*)d_in[7];
    const float* b_hh_lr  = (const float*)d_in[8];
    float* out = (float*)d_out;

    cudaFuncSetAttribute(gru_layer_kernel,
                         cudaFuncAttributeMaxDynamicSharedMemorySize, STEP_SMEM);

    for (int L = 0; L < LAYERS; L++) {
        const float *wi, *wh, *bi, *bh;
        int K, src;
        if (L == 0) {
            wi = w_ih_l0; wh = w_hh_l0; bi = b_ih_l0; bh = b_hh_l0;
            K = 256; src = 0;
        } else {
            wi = w_ih_lr + (size_t)(L - 1) * 2 * H3 * 1024;
            wh = w_hh_lr + (size_t)(L - 1) * 2 * H3 * HID;
            bi = b_ih_lr + (L - 1) * 2 * H3;
            bh = b_hh_lr + (L - 1) * 2 * H3;
            K = 1024; src = L;   // 1 -> g_y[0], 2 -> g_y[1]
        }
        int ydst = (L == 1) ? 1 : 0;   // L0->buf0, L1->buf1, L2->buf0 (unused)

        zero_h_kernel<<<64, 256>>>();

        dim3 pg(H3 / 64, (T_SEQ * BATCH) / 64, 2);
        proj_kernel<<<pg, 256>>>(x, wi, bi, K, src);

        gru_layer_kernel<<<dim3(64, 2), 256, STEP_SMEM>>>(wh, bh, out, L, ydst);
    }
}

// round 4
// speedup vs baseline: 1.0046x; 1.0046x over previous
#include <cuda_runtime.h>
#include <math.h>

// GRU problem constants
#define T_SEQ 1024
#define BATCH 32
#define HID   512
#define H3    1536   // 3*HID
#define LAYERS 3

// ---------------------------------------------------------------------------
// Scratch (device globals — no runtime allocation allowed)
// ---------------------------------------------------------------------------
// Xi for current layer, both directions: [dir][t][gate_row 0..1535][batch]
__device__ float g_xi[2][T_SEQ][H3][BATCH];
// Layer outputs (concat fwd|bwd along feature): [buf][t][batch][2H]
__device__ float g_y[2][T_SEQ][BATCH][2 * HID];
// Hidden state double buffer, stored transposed [k][batch]
__device__ float g_h[2][2][HID][BATCH];              // [buf][dir][j][b]
// Per-direction step barrier counters
__device__ unsigned g_bar[2];

// ---------------------------------------------------------------------------
// f32x2 packed-FMA helpers (sm_100+; only reachable via PTX)
// ---------------------------------------------------------------------------
__device__ __forceinline__ unsigned long long dup2(float x) {
    unsigned long long r;
    asm("mov.b64 %0, {%1, %1};" : "=l"(r) : "f"(x));
    return r;
}
__device__ __forceinline__ void ffma2(unsigned long long& d,
                                      unsigned long long a,
                                      unsigned long long b) {
    asm("fma.rn.f32x2 %0, %1, %2, %0;" : "+l"(d) : "l"(a), "l"(b));
}
__device__ __forceinline__ float2 unpk(unsigned long long v) {
    float2 f;
    asm("mov.b64 {%0, %1}, %2;" : "=f"(f.x), "=f"(f.y) : "l"(v));
    return f;
}

// ---------------------------------------------------------------------------
// Zero hidden state (both buffers, both dirs) + reset barrier counters
// ---------------------------------------------------------------------------
__global__ void zero_h_kernel() {
    int idx = blockIdx.x * blockDim.x + threadIdx.x;
    float* p = &g_h[0][0][0][0];                      // 65536 floats total
    int i = idx * 4;
    if (i < 2 * 2 * HID * BATCH) {
        *(float4*)&p[i] = make_float4(0.f, 0.f, 0.f, 0.f);
    }
    if (idx == 0) { g_bar[0] = 0u; g_bar[1] = 0u; }
}

// ---------------------------------------------------------------------------
// Input projection: Xi[d][t][g][b] = sum_k A[(t,b),k] * W[d][g][k] + b_ih[d][g]
// Tiled 64x64x16 SGEMM, 4x4 register tile, f32x2 packed FMA (j-pairs).
// src: 0 -> external x pointer, 1 -> g_y[0], 2 -> g_y[1]
// ---------------------------------------------------------------------------
__global__ __launch_bounds__(256) void proj_kernel(
    const float* __restrict__ x0,
    const float* __restrict__ W,      // (2, 1536, K)
    const float* __restrict__ bih,    // (2, 1536)
    int K, int src)
{
    const float* A = (src == 0) ? x0 : &g_y[src - 1][0][0][0];

    int d  = blockIdx.z;
    int n0 = blockIdx.x * 64;   // gate-row tile
    int m0 = blockIdx.y * 64;   // (t,b) row tile
    const float* Wd = W + (size_t)d * H3 * K;
    const float* bd = bih + d * H3;

    __shared__ float As[16][64];
    __shared__ float Bs[16][64];

    int tid  = threadIdx.x;
    int lrow = tid >> 2;            // 0..63
    int lq   = (tid & 3) << 2;      // 0,4,8,12
    int tx   = tid & 15;
    int ty   = tid >> 4;

    unsigned long long acc[4][2];   // acc[i][jp] = (c[i][2jp], c[i][2jp+1])
#pragma unroll
    for (int i = 0; i < 4; i++) { acc[i][0] = 0ull; acc[i][1] = 0ull; }

    for (int k0 = 0; k0 < K; k0 += 16) {
        float4 a4 = *(const float4*)&A [(size_t)(m0 + lrow) * K + k0 + lq];
        float4 b4 = *(const float4*)&Wd[(size_t)(n0 + lrow) * K + k0 + lq];
        As[lq + 0][lrow] = a4.x; As[lq + 1][lrow] = a4.y;
        As[lq + 2][lrow] = a4.z; As[lq + 3][lrow] = a4.w;
        Bs[lq + 0][lrow] = b4.x; Bs[lq + 1][lrow] = b4.y;
        Bs[lq + 2][lrow] = b4.z; Bs[lq + 3][lrow] = b4.w;
        __syncthreads();
#pragma unroll
        for (int kk = 0; kk < 16; kk++) {
            float4 av = *(const float4*)&As[kk][ty << 2];
            ulonglong2 bp = *(const ulonglong2*)&Bs[kk][tx << 2];
            unsigned long long a0 = dup2(av.x);
            unsigned long long a1 = dup2(av.y);
            unsigned long long a2 = dup2(av.z);
            unsigned long long a3 = dup2(av.w);
            ffma2(acc[0][0], a0, bp.x); ffma2(acc[0][1], a0, bp.y);
            ffma2(acc[1][0], a1, bp.x); ffma2(acc[1][1], a1, bp.y);
            ffma2(acc[2][0], a2, bp.x); ffma2(acc[2][1], a2, bp.y);
            ffma2(acc[3][0], a3, bp.x); ffma2(acc[3][1], a3, bp.y);
        }
        __syncthreads();
    }

#pragma unroll
    for (int i = 0; i < 4; i++) {
        int m = m0 + (ty << 2) + i;
        int t = m >> 5;
        int b = m & 31;
        float2 c01 = unpk(acc[i][0]);
        float2 c23 = unpk(acc[i][1]);
        int g = n0 + (tx << 2);
        g_xi[d][t][g + 0][b] = c01.x + bd[g + 0];
        g_xi[d][t][g + 1][b] = c01.y + bd[g + 1];
        g_xi[d][t][g + 2][b] = c23.x + bd[g + 2];
        g_xi[d][t][g + 3][b] = c23.y + bd[g + 3];
    }
}

// ---------------------------------------------------------------------------
// Persistent recurrent kernel: one launch per layer, loops all 1024 steps.
// grid = (64 j-blocks, 2 dirs) = 128 CTAs, 256 threads, 112KB dyn smem
// -> exactly 1 CTA per SM, 128 <= 148 SMs => all co-resident (spin-safe).
// W_hh slice staged to smem ONCE; h exchanged via global (__ldcg) + barrier.
// ---------------------------------------------------------------------------
#define STEP_SMEM ((3 * 8 * 512 + 512 * 32) * 4)

__global__ __launch_bounds__(256) void gru_layer_kernel(
    const float* __restrict__ whh,   // (2, 1536, 512)
    const float* __restrict__ bhh,   // (2, 1536)
    float* __restrict__ dout,        // (6, 32, 512)
    int layer, int ydst)
{
    extern __shared__ float sm[];
    float* sW = sm;                  // [3][8][512]
    float* sH = sm + 3 * 8 * 512;    // [512][32]

    int d   = blockIdx.y;
    int j0  = blockIdx.x * 8;
    int tid = threadIdx.x;
    int b   = tid & 31;
    int jl  = tid >> 5;
    int j   = j0 + jl;

    // ---- Stage W_hh rows {j0..j0+7} for gates r,z,n (once per layer) ----
    const float* wd = whh + (size_t)d * H3 * HID;
#pragma unroll
    for (int it = 0; it < 12; it++) {
        int idx  = it * 256 + tid;       // float4 units, 0..3071
        int row  = idx >> 7;             // 0..23
        int q    = (idx & 127) << 2;
        int gate = row >> 3;
        int r    = row & 7;
        *(float4*)&sW[(gate * 8 + r) * 512 + q] =
            *(const float4*)&wd[(size_t)(gate * 512 + j0 + r) * 512 + q];
    }
    const float* bd = bhh + d * H3;
    float br = bd[j], bz = bd[HID + j], bn = bd[2 * HID + j];
    const float* wr_ = &sW[(0 * 8 + jl) * 512];
    const float* wz_ = &sW[(1 * 8 + jl) * 512];
    const float* wn_ = &sW[(2 * 8 + jl) * 512];
    __syncthreads();

    unsigned target = 0;

    for (int s = 0; s < T_SEQ; s++) {
        int t = d ? (T_SEQ - 1 - s) : s;

        // Prefetch Xi for this (t, j, b) early (hides DRAM latency)
        float xr = g_xi[d][t][j][b];
        float xz = g_xi[d][t][HID + j][b];
        float xn = g_xi[d][t][2 * HID + j][b];

        // Stage h (L1-bypassing reads; written by other CTAs last step)
        const float* hin = &g_h[s & 1][d][0][0];
#pragma unroll
        for (int it = 0; it < 16; it++) {
            int idx = (it * 256 + tid) << 2;
            float4 v = __ldcg((const float4*)&hin[idx]);
            *(float4*)&sH[idx] = v;
        }
        __syncthreads();

        float ar = 0.f, az = 0.f, an = 0.f;
#pragma unroll 8
        for (int k = 0; k < HID; k += 4) {
            float4 wr = *(const float4*)&wr_[k];
            float4 wz = *(const float4*)&wz_[k];
            float4 wn = *(const float4*)&wn_[k];
            float h0 = sH[(k + 0) * 32 + b];
            float h1 = sH[(k + 1) * 32 + b];
            float h2 = sH[(k + 2) * 32 + b];
            float h3 = sH[(k + 3) * 32 + b];
            ar += wr.x * h0 + wr.y * h1 + wr.z * h2 + wr.w * h3;
            az += wz.x * h0 + wz.y * h1 + wz.z * h2 + wz.w * h3;
            an += wn.x * h0 + wn.y * h1 + wn.z * h2 + wn.w * h3;
        }

        float r = 1.f / (1.f + expf(-(xr + ar + br)));
        float z = 1.f / (1.f + expf(-(xz + az + bz)));
        float n = tanhf(xn + r * (an + bn));
        float hold = sH[j * 32 + b];
        float hnew = (1.f - z) * n + z * hold;

        g_h[(s & 1) ^ 1][d][j][b] = hnew;
        g_y[ydst][t][b][d * HID + j] = hnew;
        if (s == T_SEQ - 1) {
            dout[((layer * 2 + d) * BATCH + b) * HID + j] = hnew;
        }

        // ---- Grid barrier (per direction) ----
        __threadfence();       // make this thread's h store GPU-visible
        __syncthreads();       // all CTA threads done (canonical fence+sync)
        target += 64;
        if (tid == 0) {
            atomicAdd(&g_bar[d], 1u);
            while (((volatile unsigned*)g_bar)[d] < target) { }
        }
        __syncthreads();
        __threadfence();       // acquire: order subsequent h reads after spin
    }
}

// ---------------------------------------------------------------------------
// kernel_launch: 3 layers x (zero_h + proj + persistent layer) = 9 graph nodes
// ---------------------------------------------------------------------------
extern "C" void kernel_launch(void* const* d_in, const int* in_sizes, int n_in,
                              void* d_out, int out_size)
{
    const float* x        = (const float*)d_in[0];
    const float* w_ih_l0  = (const float*)d_in[1];
    const float* w_hh_l0  = (const float*)d_in[2];
    const float* b_ih_l0  = (const float*)d_in[3];
    const float* b_hh_l0  = (const float*)d_in[4];
    const float* w_ih_lr  = (const float*)d_in[5];
    const float* w_hh_lr  = (const float*)d_in[6];
    const float* b_ih_lr  = (const float*)d_in[7];
    const float* b_hh_lr  = (const float*)d_in[8];
    float* out = (float*)d_out;

    cudaFuncSetAttribute(gru_layer_kernel,
                         cudaFuncAttributeMaxDynamicSharedMemorySize, STEP_SMEM);

    for (int L = 0; L < LAYERS; L++) {
        const float *wi, *wh, *bi, *bh;
        int K, src;
        if (L == 0) {
            wi = w_ih_l0; wh = w_hh_l0; bi = b_ih_l0; bh = b_hh_l0;
            K = 256; src = 0;
        } else {
            wi = w_ih_lr + (size_t)(L - 1) * 2 * H3 * 1024;
            wh = w_hh_lr + (size_t)(L - 1) * 2 * H3 * HID;
            bi = b_ih_lr + (L - 1) * 2 * H3;
            bh = b_hh_lr + (L - 1) * 2 * H3;
            K = 1024; src = L;   // 1 -> g_y[0], 2 -> g_y[1]
        }
        int ydst = (L == 1) ? 1 : 0;   // L0->buf0, L1->buf1, L2->buf0 (unused)

        zero_h_kernel<<<64, 256>>>();

        dim3 pg(H3 / 64, (T_SEQ * BATCH) / 64, 2);
        proj_kernel<<<pg, 256>>>(x, wi, bi, K, src);

        gru_layer_kernel<<<dim3(64, 2), 256, STEP_SMEM>>>(wh, bh, out, L, ydst);
    }
}

// round 5
// speedup vs baseline: 1.0533x; 1.0485x over previous
#include <cuda_runtime.h>
#include <math.h>

// GRU problem constants
#define T_SEQ 1024
#define BATCH 32
#define HID   512
#define H3    1536   // 3*HID
#define LAYERS 3

// ---------------------------------------------------------------------------
// Scratch (device globals — no runtime allocation allowed)
// ---------------------------------------------------------------------------
// Xi for current layer, both directions: [dir][t][gate_row 0..1535][batch]
__device__ float g_xi[2][T_SEQ][H3][BATCH];
// Layer outputs (concat fwd|bwd along feature): [buf][t][batch][2H]
__device__ float g_y[2][T_SEQ][BATCH][2 * HID];
// Hidden state double buffer, stored b-major: [buf][dir][b][k]
__device__ float g_h[2][2][BATCH][HID];
// Per-layer, per-direction step barrier counters (padded to 128B apart)
__device__ unsigned g_bar[LAYERS][2][32];

// ---------------------------------------------------------------------------
// f32x2 packed-FMA helpers (sm_100+; only reachable via PTX)
// ---------------------------------------------------------------------------
__device__ __forceinline__ unsigned long long dup2(float x) {
    unsigned long long r;
    asm("mov.b64 %0, {%1, %1};" : "=l"(r) : "f"(x));
    return r;
}
__device__ __forceinline__ void ffma2(unsigned long long& d,
                                      unsigned long long a,
                                      unsigned long long b) {
    asm("fma.rn.f32x2 %0, %1, %2, %0;" : "+l"(d) : "l"(a), "l"(b));
}
__device__ __forceinline__ float2 unpk(unsigned long long v) {
    float2 f;
    asm("mov.b64 {%0, %1}, %2;" : "=f"(f.x), "=f"(f.y) : "l"(v));
    return f;
}

// ---------------------------------------------------------------------------
// Zero the barrier counters (h init is no longer needed: step 0 skips h)
// ---------------------------------------------------------------------------
__global__ void zero_bar_kernel() {
    int i = threadIdx.x;
    if (i < LAYERS * 2 * 32) ((unsigned*)g_bar)[i] = 0u;
}

// ---------------------------------------------------------------------------
// Input projection: Xi[d][t][g][b] = sum_k A[(t,b),k] * W[d][g][k] + b_ih[d][g]
// Tiled 64x64x16 SGEMM, 4x4 register tile, f32x2 packed FMA (j-pairs).
// src: 0 -> external x pointer, 1 -> g_y[0], 2 -> g_y[1]
// ---------------------------------------------------------------------------
__global__ __launch_bounds__(256) void proj_kernel(
    const float* __restrict__ x0,
    const float* __restrict__ W,      // (2, 1536, K)
    const float* __restrict__ bih,    // (2, 1536)
    int K, int src)
{
    const float* A = (src == 0) ? x0 : &g_y[src - 1][0][0][0];

    int d  = blockIdx.z;
    int n0 = blockIdx.x * 64;   // gate-row tile
    int m0 = blockIdx.y * 64;   // (t,b) row tile
    const float* Wd = W + (size_t)d * H3 * K;
    const float* bd = bih + d * H3;

    __shared__ float As[16][64];
    __shared__ float Bs[16][64];

    int tid  = threadIdx.x;
    int lrow = tid >> 2;            // 0..63
    int lq   = (tid & 3) << 2;      // 0,4,8,12
    int tx   = tid & 15;
    int ty   = tid >> 4;

    unsigned long long acc[4][2];   // acc[i][jp] = (c[i][2jp], c[i][2jp+1])
#pragma unroll
    for (int i = 0; i < 4; i++) { acc[i][0] = 0ull; acc[i][1] = 0ull; }

    for (int k0 = 0; k0 < K; k0 += 16) {
        float4 a4 = *(const float4*)&A [(size_t)(m0 + lrow) * K + k0 + lq];
        float4 b4 = *(const float4*)&Wd[(size_t)(n0 + lrow) * K + k0 + lq];
        As[lq + 0][lrow] = a4.x; As[lq + 1][lrow] = a4.y;
        As[lq + 2][lrow] = a4.z; As[lq + 3][lrow] = a4.w;
        Bs[lq + 0][lrow] = b4.x; Bs[lq + 1][lrow] = b4.y;
        Bs[lq + 2][lrow] = b4.z; Bs[lq + 3][lrow] = b4.w;
        __syncthreads();
#pragma unroll
        for (int kk = 0; kk < 16; kk++) {
            float4 av = *(const float4*)&As[kk][ty << 2];
            ulonglong2 bp = *(const ulonglong2*)&Bs[kk][tx << 2];
            unsigned long long a0 = dup2(av.x);
            unsigned long long a1 = dup2(av.y);
            unsigned long long a2 = dup2(av.z);
            unsigned long long a3 = dup2(av.w);
            ffma2(acc[0][0], a0, bp.x); ffma2(acc[0][1], a0, bp.y);
            ffma2(acc[1][0], a1, bp.x); ffma2(acc[1][1], a1, bp.y);
            ffma2(acc[2][0], a2, bp.x); ffma2(acc[2][1], a2, bp.y);
            ffma2(acc[3][0], a3, bp.x); ffma2(acc[3][1], a3, bp.y);
        }
        __syncthreads();
    }

#pragma unroll
    for (int i = 0; i < 4; i++) {
        int m = m0 + (ty << 2) + i;
        int t = m >> 5;
        int b = m & 31;
        float2 c01 = unpk(acc[i][0]);
        float2 c23 = unpk(acc[i][1]);
        int g = n0 + (tx << 2);
        g_xi[d][t][g + 0][b] = c01.x + bd[g + 0];
        g_xi[d][t][g + 1][b] = c01.y + bd[g + 1];
        g_xi[d][t][g + 2][b] = c23.x + bd[g + 2];
        g_xi[d][t][g + 3][b] = c23.y + bd[g + 3];
    }
}

// ---------------------------------------------------------------------------
// Persistent recurrent kernel: one launch per layer, loops all 1024 steps.
// grid = (64 j-blocks, 2 dirs) = 128 CTAs, 256 threads, ~112KB dyn smem
// -> exactly 1 CTA per SM, 128 <= 148 SMs => all co-resident (spin-safe).
// W_hh slice staged to smem ONCE. Inner GEMV uses f32x2 packed over k
// (even/odd partial sums), h staged transposed [b][k] with pad-4 rows so
// both w and h come in via conflict-free LDS.128.
// ---------------------------------------------------------------------------
#define P_H 516   // padded row length (floats) for sH: 4*516B, conflict-free f4
#define STEP_SMEM ((3 * 8 * 512 + BATCH * P_H) * 4)

__global__ __launch_bounds__(256) void gru_layer_kernel(
    const float* __restrict__ whh,   // (2, 1536, 512)
    const float* __restrict__ bhh,   // (2, 1536)
    float* __restrict__ dout,        // (6, 32, 512)
    int layer, int ydst)
{
    extern __shared__ float sm[];
    float* sW = sm;                  // [3][8][512]
    float* sH = sm + 3 * 8 * 512;    // [32][516]

    int d   = blockIdx.y;
    int j0  = blockIdx.x * 8;
    int tid = threadIdx.x;
    int b   = tid & 31;
    int jl  = tid >> 5;
    int j   = j0 + jl;

    // ---- Stage W_hh rows {j0..j0+7} for gates r,z,n (once per layer) ----
    const float* wd = whh + (size_t)d * H3 * HID;
#pragma unroll
    for (int it = 0; it < 12; it++) {
        int idx  = it * 256 + tid;       // float4 units, 0..3071
        int row  = idx >> 7;             // 0..23
        int q    = (idx & 127) << 2;
        int gate = row >> 3;
        int r    = row & 7;
        *(float4*)&sW[(gate * 8 + r) * 512 + q] =
            *(const float4*)&wd[(size_t)(gate * 512 + j0 + r) * 512 + q];
    }
    const float* bd = bhh + d * H3;
    float br = bd[j], bz = bd[HID + j], bn = bd[2 * HID + j];
    const float* wr_ = &sW[(0 * 8 + jl) * 512];
    const float* wz_ = &sW[(1 * 8 + jl) * 512];
    const float* wn_ = &sW[(2 * 8 + jl) * 512];
    const float* hb  = &sH[b * P_H];
    __syncthreads();

    volatile unsigned* barp = &g_bar[layer][d][0];
    unsigned target = 0;
    float hold = 0.f;

    int t0 = d ? (T_SEQ - 1) : 0;
    float xr = g_xi[d][t0][j][b];
    float xz = g_xi[d][t0][HID + j][b];
    float xn = g_xi[d][t0][2 * HID + j][b];

    for (int s = 0; s < T_SEQ; s++) {
        int t = d ? (T_SEQ - 1 - s) : s;

        float ar = 0.f, az = 0.f, an = 0.f;
        if (s > 0) {
            // Stage h: global [b][k] -> smem [b][k] with padded rows.
            // __ldcg: L2-coherent read (written by other SMs last step).
            const float* hin = &g_h[s & 1][d][0][0];
#pragma unroll
            for (int it = 0; it < 16; it++) {
                int idx = it * 256 + tid;          // float4 units
                float4 v = __ldcg((const float4*)&hin[idx << 2]);
                int bb = idx >> 7;
                int kq = (idx & 127) << 2;
                *(float4*)&sH[bb * P_H + kq] = v;
            }
            __syncthreads();

            unsigned long long ar2 = 0ull, az2 = 0ull, an2 = 0ull;
#pragma unroll 8
            for (int k = 0; k < HID; k += 4) {
                ulonglong2 wr = *(const ulonglong2*)&wr_[k];  // broadcast
                ulonglong2 wz = *(const ulonglong2*)&wz_[k];
                ulonglong2 wn = *(const ulonglong2*)&wn_[k];
                ulonglong2 hh = *(const ulonglong2*)&hb[k];   // conflict-free
                ffma2(ar2, wr.x, hh.x); ffma2(ar2, wr.y, hh.y);
                ffma2(az2, wz.x, hh.x); ffma2(az2, wz.y, hh.y);
                ffma2(an2, wn.x, hh.x); ffma2(an2, wn.y, hh.y);
            }
            float2 fr = unpk(ar2), fz = unpk(az2), fn = unpk(an2);
            ar = fr.x + fr.y; az = fz.x + fz.y; an = fn.x + fn.y;
        }

        float r = 1.f / (1.f + expf(-(xr + ar + br)));
        float z = 1.f / (1.f + expf(-(xz + az + bz)));
        float n = tanhf(xn + r * (an + bn));
        float hnew = (1.f - z) * n + z * hold;
        hold = hnew;

        g_h[(s & 1) ^ 1][d][b][j] = hnew;
        g_y[ydst][t][b][d * HID + j] = hnew;
        if (s == T_SEQ - 1) {
            dout[((layer * 2 + d) * BATCH + b) * HID + j] = hnew;
            break;   // nothing consumes h after the last step
        }

        // ---- Grid barrier (per layer, per direction) ----
        __syncthreads();                 // all stores issued, sH reads done
        if (tid == 0) {
            __threadfence();             // cumulative: orders whole CTA's h stores
            atomicAdd((unsigned*)barp, 1u);
        }
        // Prefetch next step's Xi while tid0 will spin
        int tn = d ? (T_SEQ - 2 - s) : (s + 1);
        float nxr = g_xi[d][tn][j][b];
        float nxz = g_xi[d][tn][HID + j][b];
        float nxn = g_xi[d][tn][2 * HID + j][b];
        target += 64;
        if (tid == 0) {
            while (*barp < target) { }
            __threadfence();             // acquire side
        }
        __syncthreads();
        xr = nxr; xz = nxz; xn = nxn;
    }
}

// ---------------------------------------------------------------------------
// kernel_launch: order = proj0, zero, zero(dummy), gru0, proj1, gru1,
// proj2, gru2  -> 8 graph nodes; ncu (-s 5 -c 1) lands on gru1.
// ---------------------------------------------------------------------------
extern "C" void kernel_launch(void* const* d_in, const int* in_sizes, int n_in,
                              void* d_out, int out_size)
{
    const float* x        = (const float*)d_in[0];
    const float* w_ih_l0  = (const float*)d_in[1];
    const float* w_hh_l0  = (const float*)d_in[2];
    const float* b_ih_l0  = (const float*)d_in[3];
    const float* b_hh_l0  = (const float*)d_in[4];
    const float* w_ih_lr  = (const float*)d_in[5];
    const float* w_hh_lr  = (const float*)d_in[6];
    const float* b_ih_lr  = (const float*)d_in[7];
    const float* b_hh_lr  = (const float*)d_in[8];
    float* out = (float*)d_out;

    cudaFuncSetAttribute(gru_layer_kernel,
                         cudaFuncAttributeMaxDynamicSharedMemorySize, STEP_SMEM);

    const float* WI[LAYERS];
    const float* WH[LAYERS];
    const float* BI[LAYERS];
    const float* BH[LAYERS];
    int KK[LAYERS], SRC[LAYERS], YD[LAYERS];
    for (int L = 0; L < LAYERS; L++) {
        if (L == 0) {
            WI[L] = w_ih_l0; WH[L] = w_hh_l0; BI[L] = b_ih_l0; BH[L] = b_hh_l0;
            KK[L] = 256; SRC[L] = 0;
        } else {
            WI[L] = w_ih_lr + (size_t)(L - 1) * 2 * H3 * 1024;
            WH[L] = w_hh_lr + (size_t)(L - 1) * 2 * H3 * HID;
            BI[L] = b_ih_lr + (L - 1) * 2 * H3;
            BH[L] = b_hh_lr + (L - 1) * 2 * H3;
            KK[L] = 1024; SRC[L] = L;
        }
        YD[L] = (L == 1) ? 1 : 0;   // L0->buf0, L1->buf1, L2->buf0 (unused)
    }

    // Layer 0 projection first (depends on nothing)
    {
        dim3 pg(H3 / 64, (T_SEQ * BATCH) / 64, 2);
        proj_kernel<<<pg, 256>>>(x, WI[0], BI[0], KK[0], SRC[0]);
    }
    // Barrier-counter reset (twice: second is a dummy to align ncu -s 5 on gru1)
    zero_bar_kernel<<<1, 192>>>();
    zero_bar_kernel<<<1, 192>>>();

    // gru0, proj1, gru1, proj2, gru2
    gru_layer_kernel<<<dim3(64, 2), 256, STEP_SMEM>>>(WH[0], BH[0], out, 0, YD[0]);
    {
        dim3 pg(H3 / 64, (T_SEQ * BATCH) / 64, 2);
        proj_kernel<<<pg, 256>>>(x, WI[1], BI[1], KK[1], SRC[1]);
    }
    gru_layer_kernel<<<dim3(64, 2), 256, STEP_SMEM>>>(WH[1], BH[1], out, 1, YD[1]);
    {
        dim3 pg(H3 / 64, (T_SEQ * BATCH) / 64, 2);
        proj_kernel<<<pg, 256>>>(x, WI[2], BI[2], KK[2], SRC[2]);
    }
    gru_layer_kernel<<<dim3(64, 2), 256, STEP_SMEM>>>(WH[2], BH[2], out, 2, YD[2]);
}